// round 11
// baseline (speedup 1.0000x reference)
#include <cuda_runtime.h>
#include <cuda_bf16.h>

// ---------------- problem constants ----------------
#define BATCH   4
#define NPTS    32768
#define NCLS    3
#define KSEL    4096          // NMS_PRE_MAXSIZE
#define KPOST   512           // NMS_POST_MAXSIZE
#define NWORDS  64            // 4096 / 64
#define NW1     16            // stage-0: first 1024 boxes
#define NBUCK   4096          // fine monotone buckets
#define CAND_CAP 6144         // smem candidate staging capacity

#define ROIS_ELEMS   (BATCH * KPOST * 7)          // 14336
#define SC_OFF       (ROIS_ELEMS)                 // 14336
#define LB_OFF       (ROIS_ELEMS + BATCH * KPOST) // 16384

// ---------------- device scratch (no allocations allowed) ----------------
__device__ int                g_hist[BATCH][NBUCK];         // 64 KB (self-zeroed by k_select)
__device__ unsigned long long g_keyfull[BATCH][NPTS];       // 1 MB
__device__ unsigned long long g_cand[BATCH][NPTS];          // overflow path only
__device__ float4             g_box4[BATCH][KSEL];          // x1,y1,x2,y2
__device__ float              g_area[BATCH][KSEL];
__device__ float              g_rois[BATCH][KSEL][7];
__device__ float              g_scores[BATCH][KSEL];
__device__ unsigned char      g_labels[BATCH][KSEL];
__device__ unsigned long long g_mask0[BATCH][1024 * NW1];   // 512 KB [row][word16]

// ---------------- helpers ----------------
__device__ __forceinline__ unsigned f2ord(float s) {
    unsigned u = __float_as_uint(s);
    return (u & 0x80000000u) ? ~u : (u | 0x80000000u);
}

// monotone (non-decreasing in u) bucket; fine resolution for s>=0.5
__device__ __forceinline__ int bucket_of(unsigned u) {
    if (u >= 0xBF000000u) {
        unsigned f = 2048u + ((u - 0xBF000000u) >> 12);
        return (int)(f > 4095u ? 4095u : f);
    }
    return (int)(u >> 21);                           // <= 1528 < 2048, monotone
}

// exact-rounding IOU>thresh, identical op order to reference
__device__ __forceinline__ bool iou_gt(float4 A, float aA, float4 B, float aB) {
    float ix = __fsub_rn(fminf(A.z, B.z), fmaxf(A.x, B.x));
    float iy = __fsub_rn(fminf(A.w, B.w), fmaxf(A.y, B.y));
    if (ix > 0.0f && iy > 0.0f) {
        float inter = __fmul_rn(ix, iy);
        float denom = __fadd_rn(__fsub_rn(__fadd_rn(aA, aB), inter), 1e-6f);
        return __fdiv_rn(inter, denom) > 0.7f;
    }
    return false;
}

// ================= K1: keys + histogram, full-chip wide ======================
// 128 blocks x 256 threads x 4 elements. Per-block smem histogram, flush
// non-zero buckets via result-unused atomicAdd (RED at L2).
__global__ void __launch_bounds__(256)
k_keys_hist(const float* __restrict__ cls) {
    __shared__ int sh[NBUCK];                        // 16 KB
    int t = threadIdx.x;
    for (int k = t; k < NBUCK; k += 256) sh[k] = 0;
    __syncthreads();

    int base = blockIdx.x * 1024;                    // block = 1024-elem chunk
    int b = base >> 15;                              // whole chunk in one batch
#pragma unroll
    for (int k = 0; k < 4; k++) {
        int gi = base + k * 256 + t;
        int i = gi & (NPTS - 1);
        const float* cp = cls + (size_t)gi * NCLS;
        float s = fmaxf(fmaxf(cp[0], cp[1]), cp[2]);
        unsigned u = f2ord(s);
        g_keyfull[b][i] = ((unsigned long long)u << 32) |
                          (unsigned long long)(0xFFFFFFFFu - (unsigned)i);
        atomicAdd(&sh[bucket_of(u)], 1);
    }
    __syncthreads();

    for (int k = t; k < NBUCK; k += 256) {
        int v = sh[k];
        if (v) atomicAdd(&g_hist[b][k], v);          // result unused -> RED
    }
}

// ================= K2: per-batch scan+scatter+rank+gather ====================
__global__ void __launch_bounds__(1024)
k_select(const float* __restrict__ boxes, const float* __restrict__ cls) {
    extern __shared__ unsigned char dsm[];
    int* s_cur  = (int*)dsm;                         // 4096 ints (scatter cursors)
    int* s_base = (int*)(dsm + 16384);               // 4096 ints
    unsigned long long* s_keys = (unsigned long long*)(dsm + 32768); // 6144 keys

    __shared__ int s_wsum[32];
    __shared__ int s_wsuf[33];
    __shared__ int s_max;

    int b = blockIdx.x, t = threadIdx.x;
    int lane = t & 31, wrp = t >> 5;
    const float* cb  = cls   + (size_t)b * NPTS * NCLS;
    const float* bx0 = boxes + (size_t)b * NPTS * 7;
    const unsigned long long* kf = g_keyfull[b];

    if (t == 0) s_max = 0;

    // ---- read histogram (coalesced), self-zero for next replay ----
    int h[4];
    int own = 0;
    const int b0 = t * 4;
#pragma unroll
    for (int k = 0; k < 4; k++) { h[k] = g_hist[b][b0 + k]; own += h[k]; }
#pragma unroll
    for (int k = 0; k < 4; k++) g_hist[b][b0 + k] = 0;

    // ---- suffix scan: warp shuffles + one cross-warp step (2 barriers) ----
    int v = own;                                     // within-warp inclusive suffix
#pragma unroll
    for (int d = 1; d < 32; d <<= 1) {
        int o = __shfl_down_sync(0xFFFFFFFFu, v, d);
        if (lane + d < 32) v += o;
    }
    if (lane == 0) s_wsum[wrp] = v;
    __syncthreads();
    if (wrp == 0) {
        int wv = s_wsum[lane];
#pragma unroll
        for (int d = 1; d < 32; d <<= 1) {
            int o = __shfl_down_sync(0xFFFFFFFFu, wv, d);
            if (lane + d < 32) wv += o;
        }
        s_wsuf[lane] = wv;                           // sum over warps >= lane
        if (lane == 0) s_wsuf[32] = 0;
    }
    __syncthreads();
    int suffix_incl = v + s_wsuf[wrp + 1];           // sum over threads >= t

    int run = suffix_incl - own;                     // strictly-above for bucket b0+3
    int lmax = 0;
#pragma unroll
    for (int k = 3; k >= 0; k--) {
        s_base[b0 + k] = run;
        s_cur[b0 + k]  = run;
        if (run < KSEL && h[k] > 0) {
            int e = run + h[k];
            if (e > lmax) lmax = e;
        }
        run += h[k];
    }
    if (lmax) atomicMax(&s_max, lmax);
    __syncthreads();

    const int candcnt = s_max;
    const int ovf = (candcnt > CAND_CAP);            // adversarial-data fallback
    unsigned long long* keys = ovf ? &g_cand[b][0] : s_keys;

    // ---- scatter precomputed keys, bucket-grouped ----
#pragma unroll 4
    for (int k = 0; k < 32; k++) {
        unsigned long long key = kf[k * 1024 + t];   // coalesced 8B loads
        int bk = bucket_of((unsigned)(key >> 32));
        if (s_base[bk] < KSEL) {
            int pos = atomicAdd(&s_cur[bk], 1);      // pos in [base, base+cnt)
            keys[pos] = key;
        }
    }
    __syncthreads();

    // ---- rank within segment + gather boxes ----
    for (int slot = t; slot < candcnt; slot += 1024) {
        unsigned long long key = keys[slot];
        unsigned u = (unsigned)(key >> 32);
        int bk = bucket_of(u);
        int segbase = s_base[bk];
        if (segbase >= KSEL) continue;               // safety
        int above = (bk > 0) ? s_base[bk - 1] : NPTS;
        int segcnt = above - segbase;
        int rank = segbase;
        if (segcnt > 1) {
            int gt = 0;
#pragma unroll 4
            for (int m = 0; m < segcnt; m++) gt += (keys[segbase + m] > key);
            rank += gt;                              // keys distinct -> unique ranks
        }
        if (rank >= KSEL) continue;

        int idx = (int)(0xFFFFFFFFu - (unsigned)key);
        const float* bx = bx0 + (size_t)idx * 7;
        float v0 = bx[0], v1 = bx[1], v2 = bx[2], v3 = bx[3],
              v4 = bx[4], v5 = bx[5], v6 = bx[6];
        float* ro = &g_rois[b][rank][0];
        ro[0] = v0; ro[1] = v1; ro[2] = v2; ro[3] = v3;
        ro[4] = v4; ro[5] = v5; ro[6] = v6;

        const float* cp = cb + (size_t)idx * NCLS;
        float c0 = cp[0], c1 = cp[1], c2 = cp[2];
        float s = c0; int lab = 0;
        if (c1 > s) { s = c1; lab = 1; }
        if (c2 > s) { s = c2; lab = 2; }
        g_scores[b][rank] = s;
        g_labels[b][rank] = (unsigned char)lab;

        float hx = __fmul_rn(0.5f, v3), hy = __fmul_rn(0.5f, v4);
        float x1 = __fsub_rn(v0, hx), x2 = __fadd_rn(v0, hx);
        float y1 = __fsub_rn(v1, hy), y2 = __fadd_rn(v1, hy);
        g_box4[b][rank] = make_float4(x1, y1, x2, y2);
        g_area[b][rank] = __fmul_rn(v3, v4);
    }
}

// ================= K3: stage-0 suppression mask (broadcast smem) =============
__global__ void __launch_bounds__(64)
k_mask0() {
    int cb = blockIdx.x, rb = blockIdx.y, b = blockIdx.z;
    if (cb < rb) return;

    __shared__ float4 sb[64];
    __shared__ float  sa[64];
    int t = threadIdx.x;
    sb[t] = g_box4[b][cb * 64 + t];
    sa[t] = g_area[b][cb * 64 + t];
    __syncthreads();

    int i = rb * 64 + t;
    float4 me = g_box4[b][i];
    float  a  = g_area[b][i];
    unsigned long long m = 0;
    int j0 = (cb == rb) ? (t + 1) : 0;               // only j > i suppressed
    for (int jj = j0; jj < 64; jj++) {               // sb[jj]: broadcast, conflict-free
        if (iou_gt(me, a, sb[jj], sa[jj])) m |= (1ull << jj);
    }
    g_mask0[b][(size_t)i * NW1 + cb] = m;
}

// ================= K4: scan stage-0 (3 barriers/word) + fallback + output ====
__global__ void __launch_bounds__(1024)
k_scan_out(float* __restrict__ out) {
    int b = blockIdx.x, tid = threadIdx.x;
    extern __shared__ unsigned char dsm[];
    float4* sbox  = (float4*)dsm;                    // fallback only: 4096*16B
    float*  sarea = (float*)(dsm + KSEL * 16);       // fallback only: 4096*4B

    __shared__ unsigned long long remv[NWORDS];
    __shared__ unsigned long long acc_s[NWORDS];
    __shared__ unsigned long long diag[64];
    __shared__ unsigned long long part[1088];        // stage0 r*17+cw ; fb colw*17+sub
    __shared__ int pref[NWORDS];
    __shared__ int s_fb;

    // zero this batch's output slice early (d_out is poisoned)
    float* rbase = out + b * KPOST * 7;
    for (int e = tid; e < KPOST * 7; e += 1024) rbase[e] = 0.0f;
    if (tid < KPOST) {
        out[SC_OFF + b * KPOST + tid] = 0.0f;
        out[LB_OFF + b * KPOST + tid] = 0.0f;
    }

    if (tid < NWORDS) { remv[tid] = 0ull; acc_s[tid] = 0ull; }
    __syncthreads();

    // ---------- stage 0: 3 barriers per word ----------
    const unsigned long long* M0 = g_mask0[b];
    int r = tid >> 4, cw = tid & 15;                 // row 0..63, col-word 0..15
    unsigned long long m = M0[(size_t)r * NW1 + cw]; // word-0 block (coalesced)

    for (int w = 0; w < NW1; w++) {
        if (cw == w) diag[r] = m;                    // diagonal for free
        __syncthreads();                             // B1: diag + prev remv ready
        if (tid == 0) {                              // serial greedy decisions
            unsigned long long rem = remv[w], acc = 0ull;
            unsigned long long dn = diag[0];
#pragma unroll
            for (int bit = 0; bit < 64; bit++) {
                unsigned long long d = dn;
                if (bit < 63) dn = diag[bit + 1];
                if (!((rem >> bit) & 1ull)) { acc |= (1ull << bit); rem |= d; }
            }
            acc_s[w] = acc;
        }
        unsigned long long mn = 0ull;                // prefetch overlaps greedy
        if (w + 1 < NW1) mn = M0[(size_t)((w + 1) * 64 + r) * NW1 + cw];
        __syncthreads();                             // B2: acc ready

        if (w + 1 < NW1) {                           // last word's OR is dead
            part[r * 17 + cw] = ((acc_s[w] >> r) & 1ull) ? m : 0ull;
            __syncthreads();                         // B3: part ready
            if (tid < NW1) {
                unsigned long long vv = remv[tid];
#pragma unroll 8
                for (int k = 0; k < 64; k++) vv |= part[k * 17 + tid];
                remv[tid] = vv;
            }
        }
        m = mn;
    }

    if (tid == 0) {
        int cnt = 0;
        for (int w = 0; w < NW1; w++) cnt += __popcll(acc_s[w]);
        s_fb = (cnt < KPOST);
    }
    __syncthreads();

    // ---------- fallback: full 4096 on-the-fly NMS (never taken normally) ----
    if (s_fb) {
        for (int i = tid; i < KSEL; i += 1024) {
            sbox[i]  = g_box4[b][i];
            sarea[i] = g_area[b][i];
        }
        if (tid < NWORDS) remv[tid] = 0ull;
        __syncthreads();

        int colw = tid >> 4, sub = tid & 15;         // 16 lanes share colw -> bcast
        for (int w = 0; w < NWORDS; w++) {
            if (tid < 64) {
                int i = w * 64 + tid;
                float4 A = sbox[i]; float aA = sarea[i];
                unsigned long long d = 0ull;
#pragma unroll 1
                for (int j = tid + 1; j < 64; j++) {
                    if (iou_gt(A, aA, sbox[w * 64 + j], sarea[w * 64 + j]))
                        d |= (1ull << j);
                }
                diag[tid] = d;
            }
            __syncthreads();
            if (tid == 0) {
                unsigned long long rem = remv[w], acc = 0ull;
#pragma unroll 1
                for (int bit = 0; bit < 64; bit++) {
                    if (!((rem >> bit) & 1ull)) { acc |= (1ull << bit); rem |= diag[bit]; }
                }
                acc_s[w] = acc;
            }
            __syncthreads();

            unsigned long long acc = acc_s[w];
            unsigned long long p = 0ull;
            if (colw > w) {
#pragma unroll 1
                for (int rr = 0; rr < 4; rr++) {
                    int rbit = sub + rr * 16;
                    if ((acc >> rbit) & 1ull) {
                        int i = w * 64 + rbit;
                        float4 A = sbox[i]; float aA = sarea[i];
#pragma unroll 1
                        for (int j = 0; j < 64; j++) {
                            if (iou_gt(A, aA, sbox[colw * 64 + j], sarea[colw * 64 + j]))
                                p |= (1ull << j);
                        }
                    }
                }
            }
            part[colw * 17 + sub] = p;
            __syncthreads();
            if (tid < 64) {
                unsigned long long vv = remv[tid];
#pragma unroll 1
                for (int k = 0; k < 16; k++) vv |= part[tid * 17 + k];
                remv[tid] = vv;
            }
            __syncthreads();
        }
    }

    // ---------- compact + output ----------
    if (tid == 0) {
        int s = 0;
        for (int w = 0; w < NWORDS; w++) { pref[w] = s; s += __popcll(acc_s[w]); }
    }
    __syncthreads();

    if (tid < NWORDS) {
        unsigned long long a = acc_s[tid];
        int rank = pref[tid];
        while (a && rank < KPOST) {
            int bit = __ffsll((long long)a) - 1;
            a &= a - 1;
            int i = tid * 64 + bit;
            const float* ro = &g_rois[b][i][0];
            int obase = (b * KPOST + rank) * 7;
#pragma unroll
            for (int c = 0; c < 7; c++) out[obase + c] = ro[c];
            out[SC_OFF + b * KPOST + rank] = g_scores[b][i];
            out[LB_OFF + b * KPOST + rank] = (float)(g_labels[b][i] + 1);
            rank++;
        }
    }
}

// ---------------- launch (4 kernels) ----------------
extern "C" void kernel_launch(void* const* d_in, const int* in_sizes, int n_in,
                              void* d_out, int out_size) {
    const float* boxes = (const float*)d_in[0];
    const float* cls   = (const float*)d_in[1];
    if (n_in >= 2 && in_sizes[0] == BATCH * NPTS * NCLS) {
        boxes = (const float*)d_in[1];
        cls   = (const float*)d_in[0];
    }
    float* out = (float*)d_out;

    const int DSM_SEL  = 16384 + 16384 + CAND_CAP * 8;   // 81920 B
    const int DSM_SCAN = KSEL * 16 + KSEL * 4;           // 81920 B (fallback boxes)

    cudaFuncSetAttribute(k_select,
                         cudaFuncAttributeMaxDynamicSharedMemorySize, DSM_SEL);
    cudaFuncSetAttribute(k_scan_out,
                         cudaFuncAttributeMaxDynamicSharedMemorySize, DSM_SCAN);

    k_keys_hist<<<BATCH * NPTS / 1024, 256>>>(cls);
    k_select<<<BATCH, 1024, DSM_SEL>>>(boxes, cls);
    k_mask0<<<dim3(NW1, NW1, BATCH), 64>>>();
    k_scan_out<<<BATCH, 1024, DSM_SCAN>>>(out);
}

// round 12
// speedup vs baseline: 1.2267x; 1.2267x over previous
#include <cuda_runtime.h>
#include <cuda_bf16.h>

// ---------------- problem constants ----------------
#define BATCH   4
#define NPTS    32768
#define NCLS    3
#define KSEL    4096          // NMS_PRE_MAXSIZE
#define KPOST   512           // NMS_POST_MAXSIZE
#define NWORDS  64            // 4096 / 64
#define NW1     16            // stage-0: first 1024 boxes
#define NBUCK   4096          // fine monotone buckets
#define CAND_CAP 6144         // smem candidate staging capacity
#define MSW     1088          // padded smem stride per mask word (64*17)

#define ROIS_ELEMS   (BATCH * KPOST * 7)          // 14336
#define SC_OFF       (ROIS_ELEMS)                 // 14336
#define LB_OFF       (ROIS_ELEMS + BATCH * KPOST) // 16384

// ---------------- device scratch (no allocations allowed) ----------------
__device__ int                g_hist[BATCH][NBUCK];         // self-zeroed by k_select
__device__ unsigned long long g_keyfull[BATCH][NPTS];       // 1 MB
__device__ unsigned long long g_cand[BATCH][NPTS];          // overflow path only
__device__ float4             g_box4[BATCH][KSEL];          // x1,y1,x2,y2
__device__ float              g_area[BATCH][KSEL];
__device__ float              g_rois[BATCH][KSEL][7];
__device__ float              g_scores[BATCH][KSEL];
__device__ unsigned char      g_labels[BATCH][KSEL];
__device__ unsigned long long g_mask0[BATCH][1024 * NW1];   // 512 KB [row][word16]
                                                            // lower-tri blocks stay 0

// ---------------- helpers ----------------
__device__ __forceinline__ unsigned f2ord(float s) {
    unsigned u = __float_as_uint(s);
    return (u & 0x80000000u) ? ~u : (u | 0x80000000u);
}

// monotone (non-decreasing in u) bucket; fine resolution for s>=0.5
__device__ __forceinline__ int bucket_of(unsigned u) {
    if (u >= 0xBF000000u) {
        unsigned f = 2048u + ((u - 0xBF000000u) >> 12);
        return (int)(f > 4095u ? 4095u : f);
    }
    return (int)(u >> 21);                           // <= 1528 < 2048, monotone
}

// exact-rounding IOU>thresh, identical op order to reference
__device__ __forceinline__ bool iou_gt(float4 A, float aA, float4 B, float aB) {
    float ix = __fsub_rn(fminf(A.z, B.z), fmaxf(A.x, B.x));
    float iy = __fsub_rn(fminf(A.w, B.w), fmaxf(A.y, B.y));
    if (ix > 0.0f && iy > 0.0f) {
        float inter = __fmul_rn(ix, iy);
        float denom = __fadd_rn(__fsub_rn(__fadd_rn(aA, aB), inter), 1e-6f);
        return __fdiv_rn(inter, denom) > 0.7f;
    }
    return false;
}

// ================= K1: keys + histogram, full-chip wide (R10 form) ===========
__global__ void __launch_bounds__(256)
k_keys_hist(const float* __restrict__ cls) {
    __shared__ int sh[NBUCK];                        // 16 KB
    int t = threadIdx.x;
    for (int k = t; k < NBUCK; k += 256) sh[k] = 0;
    __syncthreads();

    int gi = blockIdx.x * 256 + t;                   // 0 .. 131071
    int b = gi >> 15, i = gi & (NPTS - 1);
    const float* cp = cls + (size_t)gi * NCLS;
    float s = fmaxf(fmaxf(cp[0], cp[1]), cp[2]);
    unsigned u = f2ord(s);
    g_keyfull[b][i] = ((unsigned long long)u << 32) |
                      (unsigned long long)(0xFFFFFFFFu - (unsigned)i);
    atomicAdd(&sh[bucket_of(u)], 1);
    __syncthreads();

    for (int k = t; k < NBUCK; k += 256) {           // block all in one batch
        int v = sh[k];
        if (v) atomicAdd(&g_hist[b][k], v);          // result unused -> RED
    }
}

// ================= K2: per-batch scan+scatter+rank+gather ====================
__global__ void __launch_bounds__(1024)
k_select(const float* __restrict__ boxes, const float* __restrict__ cls) {
    extern __shared__ unsigned char dsm[];
    int* s_cur  = (int*)dsm;                         // 4096 ints (scatter cursors)
    int* s_base = (int*)(dsm + 16384);               // 4096 ints
    unsigned long long* s_keys = (unsigned long long*)(dsm + 32768); // 6144 keys

    __shared__ int s_wsum[32];
    __shared__ int s_wsuf[33];
    __shared__ int s_max;

    int b = blockIdx.x, t = threadIdx.x;
    int lane = t & 31, wrp = t >> 5;
    const float* cb  = cls   + (size_t)b * NPTS * NCLS;
    const float* bx0 = boxes + (size_t)b * NPTS * 7;
    const unsigned long long* kf = g_keyfull[b];

    if (t == 0) s_max = 0;

    // ---- read histogram (coalesced), self-zero for next replay ----
    int h[4];
    int own = 0;
    const int b0 = t * 4;
#pragma unroll
    for (int k = 0; k < 4; k++) { h[k] = g_hist[b][b0 + k]; own += h[k]; }
#pragma unroll
    for (int k = 0; k < 4; k++) g_hist[b][b0 + k] = 0;

    // ---- suffix scan: warp shuffles + one cross-warp step ----
    int v = own;
#pragma unroll
    for (int d = 1; d < 32; d <<= 1) {
        int o = __shfl_down_sync(0xFFFFFFFFu, v, d);
        if (lane + d < 32) v += o;
    }
    if (lane == 0) s_wsum[wrp] = v;
    __syncthreads();
    if (wrp == 0) {
        int wv = s_wsum[lane];
#pragma unroll
        for (int d = 1; d < 32; d <<= 1) {
            int o = __shfl_down_sync(0xFFFFFFFFu, wv, d);
            if (lane + d < 32) wv += o;
        }
        s_wsuf[lane] = wv;                           // sum over warps >= lane
        if (lane == 0) s_wsuf[32] = 0;
    }
    __syncthreads();
    int suffix_incl = v + s_wsuf[wrp + 1];           // sum over threads >= t

    int run = suffix_incl - own;
    int lmax = 0;
#pragma unroll
    for (int k = 3; k >= 0; k--) {
        s_base[b0 + k] = run;
        s_cur[b0 + k]  = run;
        if (run < KSEL && h[k] > 0) {
            int e = run + h[k];
            if (e > lmax) lmax = e;
        }
        run += h[k];
    }
    if (lmax) atomicMax(&s_max, lmax);
    __syncthreads();

    const int candcnt = s_max;
    const int ovf = (candcnt > CAND_CAP);            // adversarial-data fallback
    unsigned long long* keys = ovf ? &g_cand[b][0] : s_keys;

    // ---- scatter precomputed keys, bucket-grouped ----
#pragma unroll 4
    for (int k = 0; k < 32; k++) {
        unsigned long long key = kf[k * 1024 + t];   // coalesced 8B loads
        int bk = bucket_of((unsigned)(key >> 32));
        if (s_base[bk] < KSEL) {
            int pos = atomicAdd(&s_cur[bk], 1);      // pos in [base, base+cnt)
            keys[pos] = key;
        }
    }
    __syncthreads();

    // ---- rank within segment + gather boxes ----
    for (int slot = t; slot < candcnt; slot += 1024) {
        unsigned long long key = keys[slot];
        unsigned u = (unsigned)(key >> 32);
        int bk = bucket_of(u);
        int segbase = s_base[bk];
        if (segbase >= KSEL) continue;               // safety
        int above = (bk > 0) ? s_base[bk - 1] : NPTS;
        int segcnt = above - segbase;
        int rank = segbase;
        if (segcnt > 1) {
            int gt = 0;
#pragma unroll 4
            for (int m = 0; m < segcnt; m++) gt += (keys[segbase + m] > key);
            rank += gt;                              // keys distinct -> unique ranks
        }
        if (rank >= KSEL) continue;

        int idx = (int)(0xFFFFFFFFu - (unsigned)key);
        const float* bx = bx0 + (size_t)idx * 7;
        float v0 = bx[0], v1 = bx[1], v2 = bx[2], v3 = bx[3],
              v4 = bx[4], v5 = bx[5], v6 = bx[6];
        float* ro = &g_rois[b][rank][0];
        ro[0] = v0; ro[1] = v1; ro[2] = v2; ro[3] = v3;
        ro[4] = v4; ro[5] = v5; ro[6] = v6;

        const float* cp = cb + (size_t)idx * NCLS;
        float c0 = cp[0], c1 = cp[1], c2 = cp[2];
        float s = c0; int lab = 0;
        if (c1 > s) { s = c1; lab = 1; }
        if (c2 > s) { s = c2; lab = 2; }
        g_scores[b][rank] = s;
        g_labels[b][rank] = (unsigned char)lab;

        float hx = __fmul_rn(0.5f, v3), hy = __fmul_rn(0.5f, v4);
        float x1 = __fsub_rn(v0, hx), x2 = __fadd_rn(v0, hx);
        float y1 = __fsub_rn(v1, hy), y2 = __fadd_rn(v1, hy);
        g_box4[b][rank] = make_float4(x1, y1, x2, y2);
        g_area[b][rank] = __fmul_rn(v3, v4);
    }
}

// ================= K3: stage-0 suppression mask (broadcast smem) =============
__global__ void __launch_bounds__(64)
k_mask0() {
    int cb = blockIdx.x, rb = blockIdx.y, b = blockIdx.z;
    if (cb < rb) return;

    __shared__ float4 sb[64];
    __shared__ float  sa[64];
    int t = threadIdx.x;
    sb[t] = g_box4[b][cb * 64 + t];
    sa[t] = g_area[b][cb * 64 + t];
    __syncthreads();

    int i = rb * 64 + t;
    float4 me = g_box4[b][i];
    float  a  = g_area[b][i];
    unsigned long long m = 0;
    int j0 = (cb == rb) ? (t + 1) : 0;               // only j > i suppressed
    for (int jj = j0; jj < 64; jj++) {               // sb[jj]: broadcast, conflict-free
        if (iou_gt(me, a, sb[jj], sa[jj])) m |= (1ull << jj);
    }
    g_mask0[b][(size_t)i * NW1 + cb] = m;
}

// ================= K4: SPARSE scan stage-0 + fallback + compact + output =====
// Masks cached in padded smem; nz (rows with nonzero diag) via one ballot pass;
// per word: sparse greedy on thread 0 (chain = #nonzero-diag rows, ~2-4) and a
// sparse atomicOr scatter instead of a dense 64-iter OR reduction.
__global__ void __launch_bounds__(1024)
k_scan_out(float* __restrict__ out) {
    int b = blockIdx.x, tid = threadIdx.x;
    extern __shared__ unsigned char dsm[];
    unsigned long long* ms = (unsigned long long*)dsm;   // stage0: 16*MSW words
    float4* sbox  = (float4*)dsm;                        // fallback alias
    float*  sarea = (float*)(dsm + KSEL * 16);           // fallback alias

    __shared__ unsigned long long remv[NWORDS];
    __shared__ unsigned long long acc_s[NWORDS];
    __shared__ unsigned long long diag[64];              // fallback only
    __shared__ unsigned long long part[1088];            // fallback only
    __shared__ unsigned nzlo[NW1], nzhi[NW1];
    __shared__ int pref[NWORDS];
    __shared__ int s_fb;

    // zero this batch's output slice early (d_out is poisoned)
    float* rbase = out + b * KPOST * 7;
    for (int e = tid; e < KPOST * 7; e += 1024) rbase[e] = 0.0f;
    if (tid < KPOST) {
        out[SC_OFF + b * KPOST + tid] = 0.0f;
        out[LB_OFF + b * KPOST + tid] = 0.0f;
    }
    if (tid < NWORDS) { remv[tid] = 0ull; acc_s[tid] = 0ull; }

    // ---- bulk copy masks into padded smem (conflict-free layout) ----
    const unsigned long long* M0 = g_mask0[b];
    int r4 = tid >> 4, cw4 = tid & 15;                   // row-in-word, col-word
#pragma unroll
    for (int k = 0; k < NW1; k++)
        ms[k * MSW + r4 * 17 + cw4] = M0[k * 1024 + tid];
    __syncthreads();

    // ---- nz for all 16 words in one ballot pass ----
    {
        int w = tid >> 6, r = tid & 63;                  // warp = 2w + (r>=32)
        unsigned long long dv = ms[w * MSW + r * 17 + w];
        unsigned bal = __ballot_sync(0xFFFFFFFFu, dv != 0ull);
        if ((tid & 31) == 0) {
            if (r < 32) nzlo[w] = bal; else nzhi[w] = bal;
        }
    }
    __syncthreads();

    // ---- stage 0: 16 words, sparse greedy + sparse OR ----
    for (int w = 0; w < NW1; w++) {
        if (tid == 0) {
            unsigned long long rem = remv[w];
            unsigned long long nz =
                ((unsigned long long)nzhi[w] << 32) | (unsigned long long)nzlo[w];
            unsigned long long work = nz & ~rem;
            const unsigned long long* dg = &ms[w * MSW];
            while (work) {                               // ~2-4 iterations typical
                int bit = __ffsll((long long)work) - 1;
                unsigned long long d = dg[bit * 17 + w];
                rem |= d;                                // d has only bits > bit
                work &= ~rem;
                work &= ~(1ull << bit);
            }
            acc_s[w] = ~rem;                             // accepted = not suppressed
        }
        __syncthreads();                                 // B1: acc ready
        if (cw4 > w) {                                   // upper-tri only (valid data)
            unsigned long long m = ms[w * MSW + r4 * 17 + cw4];
            if (m && ((acc_s[w] >> r4) & 1ull))
                atomicOr(&remv[cw4], m);                 // sparse: rare
        }
        __syncthreads();                                 // B2: remv final for w+1
    }

    if (tid == 0) {
        int cnt = 0;
        for (int w = 0; w < NW1; w++) cnt += __popcll(acc_s[w]);
        s_fb = (cnt < KPOST);
    }
    __syncthreads();

    // ---------- fallback: full 4096 on-the-fly NMS (never taken normally) ----
    if (s_fb) {
        for (int i = tid; i < KSEL; i += 1024) {         // overwrites ms region
            sbox[i]  = g_box4[b][i];
            sarea[i] = g_area[b][i];
        }
        if (tid < NWORDS) remv[tid] = 0ull;
        __syncthreads();

        int colw = tid >> 4, sub = tid & 15;             // 16 lanes share colw
        for (int w = 0; w < NWORDS; w++) {
            if (tid < 64) {
                int i = w * 64 + tid;
                float4 A = sbox[i]; float aA = sarea[i];
                unsigned long long d = 0ull;
#pragma unroll 1
                for (int j = tid + 1; j < 64; j++) {
                    if (iou_gt(A, aA, sbox[w * 64 + j], sarea[w * 64 + j]))
                        d |= (1ull << j);
                }
                diag[tid] = d;
            }
            __syncthreads();
            if (tid == 0) {
                unsigned long long rem = remv[w], acc = 0ull;
#pragma unroll 1
                for (int bit = 0; bit < 64; bit++) {
                    if (!((rem >> bit) & 1ull)) { acc |= (1ull << bit); rem |= diag[bit]; }
                }
                acc_s[w] = acc;
            }
            __syncthreads();

            unsigned long long acc = acc_s[w];
            unsigned long long p = 0ull;
            if (colw > w) {
#pragma unroll 1
                for (int rr = 0; rr < 4; rr++) {
                    int rbit = sub + rr * 16;
                    if ((acc >> rbit) & 1ull) {
                        int i = w * 64 + rbit;
                        float4 A = sbox[i]; float aA = sarea[i];
#pragma unroll 1
                        for (int j = 0; j < 64; j++) {
                            if (iou_gt(A, aA, sbox[colw * 64 + j], sarea[colw * 64 + j]))
                                p |= (1ull << j);
                        }
                    }
                }
            }
            part[colw * 17 + sub] = p;
            __syncthreads();
            if (tid < 64) {
                unsigned long long vv = remv[tid];
#pragma unroll 1
                for (int k = 0; k < 16; k++) vv |= part[tid * 17 + k];
                remv[tid] = vv;
            }
            __syncthreads();
        }
    }

    // ---------- compact + output ----------
    if (tid == 0) {
        int s = 0;
        for (int w = 0; w < NWORDS; w++) { pref[w] = s; s += __popcll(acc_s[w]); }
    }
    __syncthreads();

    if (tid < NWORDS) {
        unsigned long long a = acc_s[tid];
        int rank = pref[tid];
        while (a && rank < KPOST) {
            int bit = __ffsll((long long)a) - 1;
            a &= a - 1;
            int i = tid * 64 + bit;
            const float* ro = &g_rois[b][i][0];
            int obase = (b * KPOST + rank) * 7;
#pragma unroll
            for (int c = 0; c < 7; c++) out[obase + c] = ro[c];
            out[SC_OFF + b * KPOST + rank] = g_scores[b][i];
            out[LB_OFF + b * KPOST + rank] = (float)(g_labels[b][i] + 1);
            rank++;
        }
    }
}

// ---------------- launch (4 kernels) ----------------
extern "C" void kernel_launch(void* const* d_in, const int* in_sizes, int n_in,
                              void* d_out, int out_size) {
    const float* boxes = (const float*)d_in[0];
    const float* cls   = (const float*)d_in[1];
    if (n_in >= 2 && in_sizes[0] == BATCH * NPTS * NCLS) {
        boxes = (const float*)d_in[1];
        cls   = (const float*)d_in[0];
    }
    float* out = (float*)d_out;

    const int DSM_SEL  = 16384 + 16384 + CAND_CAP * 8;   // 81920 B
    const int DSM_SCAN = NW1 * MSW * 8;                  // 139264 B (masks; >80KB fb)

    cudaFuncSetAttribute(k_select,
                         cudaFuncAttributeMaxDynamicSharedMemorySize, DSM_SEL);
    cudaFuncSetAttribute(k_scan_out,
                         cudaFuncAttributeMaxDynamicSharedMemorySize, DSM_SCAN);

    k_keys_hist<<<BATCH * NPTS / 256, 256>>>(cls);
    k_select<<<BATCH, 1024, DSM_SEL>>>(boxes, cls);
    k_mask0<<<dim3(NW1, NW1, BATCH), 64>>>();
    k_scan_out<<<BATCH, 1024, DSM_SCAN>>>(out);
}